// round 1
// baseline (speedup 1.0000x reference)
#include <cuda_runtime.h>
#include <math.h>

#define NB 4
#define LL 4096
#define CC 512
#define HH 8
#define HD 64
#define ML (NB*LL)            // 16384 rows
#define NCH 8                 // KV split-S chunks
#define NHT (NB*HH)           // 32 (n,h) pairs

// ---------------- scratch (device globals; no allocation) ----------------
__device__ float g_Q  [ML*CC];
__device__ float g_K  [ML*CC];
__device__ float g_V  [ML*CC];
__device__ float g_msg[ML*CC];
__device__ float g_m2 [ML*CC];
__device__ float g_cat[ML*2*CC];
__device__ float g_h1 [ML*2*CC];
__device__ float g_h2 [ML*CC];
__device__ float g_pKV[NCH*NHT*HD*HD];
__device__ float g_pKs[NCH*NHT*HD];
__device__ float g_KV [NHT*HD*HD];
__device__ float g_Ks [NHT*HD];

// ---------------- generic SGEMM: C[M,N] = A[M,K] @ B[N,K]^T --------------
// EPI: 0 none, 1 elu(t)+1, 2 scale by param, 3 relu
template<int EPI>
__global__ void __launch_bounds__(256) sgemm_tn(
    const float* __restrict__ A, const float* __restrict__ B,
    float* __restrict__ C, int M, int N, int K, float param)
{
    __shared__ float As[16][128];
    __shared__ float Bs[16][128];
    const int tid = threadIdx.x;
    const int tx = tid & 15, ty = tid >> 4;
    const int m0 = blockIdx.y * 128, n0 = blockIdx.x * 128;

    float acc[8][8];
#pragma unroll
    for (int i = 0; i < 8; i++)
#pragma unroll
        for (int j = 0; j < 8; j++) acc[i][j] = 0.f;

    for (int k0 = 0; k0 < K; k0 += 16) {
#pragma unroll
        for (int u = 0; u < 2; u++) {
            int idx = tid * 2 + u;          // 0..511
            int r   = idx >> 2;             // 0..127
            int c4  = idx & 3;              // 0..3
            float4 av = *(const float4*)(A + (size_t)(m0 + r) * K + k0 + c4 * 4);
            As[c4*4+0][r] = av.x; As[c4*4+1][r] = av.y;
            As[c4*4+2][r] = av.z; As[c4*4+3][r] = av.w;
            float4 bv = *(const float4*)(B + (size_t)(n0 + r) * K + k0 + c4 * 4);
            Bs[c4*4+0][r] = bv.x; Bs[c4*4+1][r] = bv.y;
            Bs[c4*4+2][r] = bv.z; Bs[c4*4+3][r] = bv.w;
        }
        __syncthreads();
#pragma unroll
        for (int k = 0; k < 16; k++) {
            float a[8], b[8];
            float4 t;
            t = *(const float4*)&As[k][ty*8];   a[0]=t.x; a[1]=t.y; a[2]=t.z; a[3]=t.w;
            t = *(const float4*)&As[k][ty*8+4]; a[4]=t.x; a[5]=t.y; a[6]=t.z; a[7]=t.w;
            t = *(const float4*)&Bs[k][tx*8];   b[0]=t.x; b[1]=t.y; b[2]=t.z; b[3]=t.w;
            t = *(const float4*)&Bs[k][tx*8+4]; b[4]=t.x; b[5]=t.y; b[6]=t.z; b[7]=t.w;
#pragma unroll
            for (int i = 0; i < 8; i++)
#pragma unroll
                for (int j = 0; j < 8; j++) acc[i][j] += a[i] * b[j];
        }
        __syncthreads();
    }

#pragma unroll
    for (int i = 0; i < 8; i++) {
        int r = m0 + ty*8 + i;
#pragma unroll
        for (int j = 0; j < 8; j++) {
            float v = acc[i][j];
            if (EPI == 1) v = (v > 0.f) ? (v + 1.f) : expf(v);   // elu(t)+1
            else if (EPI == 2) v *= param;
            else if (EPI == 3) v = fmaxf(v, 0.f);
            acc[i][j] = v;
        }
        float* cp = C + (size_t)r * N + n0 + tx*8;
        *(float4*)(cp)     = make_float4(acc[i][0], acc[i][1], acc[i][2], acc[i][3]);
        *(float4*)(cp + 4) = make_float4(acc[i][4], acc[i][5], acc[i][6], acc[i][7]);
    }
}

// -------- KV partial: per (chunk, n, h): KV += K^T V over 512 rows --------
__global__ void __launch_bounds__(256) kv_partial(
    const float* __restrict__ Kb, const float* __restrict__ Vb,
    float* __restrict__ pKV, float* __restrict__ pKs)
{
    __shared__ float Ks[32][64];
    __shared__ float Vs[32][64];
    const int tid = threadIdx.x;
    const int ch = blockIdx.x, h = blockIdx.y, n = blockIdx.z;
    const int nh = n * HH + h;
    const float* Kp = Kb + ((size_t)n * LL + ch * 512) * CC + h * HD;
    const float* Vp = Vb + ((size_t)n * LL + ch * 512) * CC + h * HD;

    const int d0 = (tid >> 4) * 4, v0 = (tid & 15) * 4;
    float acc[4][4] = {};
    float ks[4] = {0.f, 0.f, 0.f, 0.f};

    for (int s0 = 0; s0 < 512; s0 += 32) {
#pragma unroll
        for (int u = 0; u < 2; u++) {
            int idx = tid * 2 + u;          // 0..511
            int r = idx >> 4, c4 = idx & 15;
            *(float4*)&Ks[r][c4*4] = *(const float4*)(Kp + (size_t)(s0 + r) * CC + c4 * 4);
            *(float4*)&Vs[r][c4*4] = *(const float4*)(Vp + (size_t)(s0 + r) * CC + c4 * 4);
        }
        __syncthreads();
#pragma unroll 8
        for (int s = 0; s < 32; s++) {
            float4 kk = *(const float4*)&Ks[s][d0];
            float4 vv = *(const float4*)&Vs[s][v0];
            float ka[4] = {kk.x, kk.y, kk.z, kk.w};
            float va[4] = {vv.x, vv.y, vv.z, vv.w};
#pragma unroll
            for (int i = 0; i < 4; i++) {
                ks[i] += ka[i];
#pragma unroll
                for (int j = 0; j < 4; j++) acc[i][j] += ka[i] * va[j];
            }
        }
        __syncthreads();
    }
    float* o = pKV + ((size_t)ch * NHT + nh) * HD * HD;
#pragma unroll
    for (int i = 0; i < 4; i++)
        *(float4*)(o + (d0 + i) * HD + v0) =
            make_float4(acc[i][0], acc[i][1], acc[i][2], acc[i][3]);
    if ((tid & 15) == 0) {
        float* ok = pKs + ((size_t)ch * NHT + nh) * HD + d0;
#pragma unroll
        for (int i = 0; i < 4; i++) ok[i] = ks[i];
    }
}

// -------- deterministic reduction of the 8 chunks --------
__global__ void kv_reduce(const float* __restrict__ pKV, const float* __restrict__ pKs,
                          float* __restrict__ KV, float* __restrict__ Ksum)
{
    const int idx = blockIdx.x * 256 + threadIdx.x;
    const int nKV = NHT * HD * HD;          // 131072
    if (idx < nKV) {
        float s = 0.f;
#pragma unroll
        for (int c = 0; c < NCH; c++) s += pKV[(size_t)c * nKV + idx];
        KV[idx] = s;
    } else if (idx < nKV + NHT * HD) {
        int j = idx - nKV;
        float s = 0.f;
#pragma unroll
        for (int c = 0; c < NCH; c++) s += pKs[(size_t)c * NHT * HD + j];
        Ksum[j] = s;
    }
}

// -------- fused message: msg = (Q @ KV) * S/(Q.Ksum + eps) --------
__global__ void __launch_bounds__(256) msg_kernel(
    const float* __restrict__ Q, const float* __restrict__ KV,
    const float* __restrict__ Ksum, float* __restrict__ msg)
{
    __shared__ float Qs[64][64];
    __shared__ float KVs[64][64];
    __shared__ float Kss[64];
    const int tid = threadIdx.x;
    const int lt = blockIdx.x, h = blockIdx.y, n = blockIdx.z;
    const int nh = n * HH + h;
    const float* Qp  = Q  + ((size_t)n * LL + lt * 64) * CC + h * HD;
    const float* KVp = KV + (size_t)nh * HD * HD;

#pragma unroll
    for (int u = 0; u < 4; u++) {
        int idx = u * 256 + tid;           // 0..1023 float4 slots
        int r = idx >> 4, c4 = idx & 15;
        *(float4*)&Qs[r][c4*4]  = *(const float4*)(Qp  + (size_t)r * CC + c4 * 4);
        *(float4*)&KVs[r][c4*4] = *(const float4*)(KVp + r * HD + c4 * 4);
    }
    if (tid < 64) Kss[tid] = Ksum[(size_t)nh * HD + tid];
    __syncthreads();

    const int r0 = (tid >> 4) * 4, c0 = (tid & 15) * 4;
    float acc[4][4] = {};
    float z[4] = {0.f, 0.f, 0.f, 0.f};
#pragma unroll 16
    for (int k = 0; k < 64; k++) {
        float4 bb = *(const float4*)&KVs[k][c0];
        float b[4] = {bb.x, bb.y, bb.z, bb.w};
        float ksk = Kss[k];
#pragma unroll
        for (int i = 0; i < 4; i++) {
            float a = Qs[r0 + i][k];
            z[i] += a * ksk;
#pragma unroll
            for (int j = 0; j < 4; j++) acc[i][j] += a * b[j];
        }
    }
#pragma unroll
    for (int i = 0; i < 4; i++) {
        float sc = (float)LL / (z[i] + 1e-6f);   // S * 1/(dot + EPS)
        float* mp = msg + ((size_t)(n * LL + lt * 64 + r0 + i)) * CC + h * HD + c0;
        *(float4*)mp = make_float4(acc[i][0]*sc, acc[i][1]*sc, acc[i][2]*sc, acc[i][3]*sc);
    }
}

// -------- LayerNorm (optionally + residual), 1 warp per 512-row --------
__global__ void __launch_bounds__(256) ln_kernel(
    const float* __restrict__ in, float* __restrict__ out,
    const float* __restrict__ g, const float* __restrict__ b,
    const float* __restrict__ resid)
{
    const int row  = (blockIdx.x * 256 + threadIdx.x) >> 5;
    const int lane = threadIdx.x & 31;
    if (row >= ML) return;
    const float* p = in + (size_t)row * CC;
    float v[16];
#pragma unroll
    for (int u = 0; u < 4; u++) {
        float4 t = *(const float4*)(p + u * 128 + lane * 4);
        v[u*4+0] = t.x; v[u*4+1] = t.y; v[u*4+2] = t.z; v[u*4+3] = t.w;
    }
    float s = 0.f, sq = 0.f;
#pragma unroll
    for (int i = 0; i < 16; i++) { s += v[i]; sq += v[i] * v[i]; }
#pragma unroll
    for (int off = 16; off >= 1; off >>= 1) {
        s  += __shfl_xor_sync(0xFFFFFFFFu, s,  off);
        sq += __shfl_xor_sync(0xFFFFFFFFu, sq, off);
    }
    const float mu  = s * (1.f / CC);
    const float var = sq * (1.f / CC) - mu * mu;
    const float rs  = rsqrtf(var + 1e-5f);
    float* o = out + (size_t)row * CC;
#pragma unroll
    for (int u = 0; u < 4; u++) {
        int c = u * 128 + lane * 4;
        float4 go = *(const float4*)(g + c);
        float4 bo = *(const float4*)(b + c);
        float4 r;
        r.x = (v[u*4+0] - mu) * rs * go.x + bo.x;
        r.y = (v[u*4+1] - mu) * rs * go.y + bo.y;
        r.z = (v[u*4+2] - mu) * rs * go.z + bo.z;
        r.w = (v[u*4+3] - mu) * rs * go.w + bo.w;
        if (resid) {
            float4 rx = *(const float4*)(resid + (size_t)row * CC + c);
            r.x += rx.x; r.y += rx.y; r.z += rx.z; r.w += rx.w;
        }
        *(float4*)(o + c) = r;
    }
}

// -------- concat(x, msg_ln) -> [ML, 2C] --------
__global__ void __launch_bounds__(256) concat_kernel(
    const float* __restrict__ x, const float* __restrict__ m, float* __restrict__ cat)
{
    const int idx = blockIdx.x * 256 + threadIdx.x;   // float4 slot, 16384*256 total
    const int row = idx >> 8;
    const int c4  = idx & 255;
    float4 v;
    if (c4 < 128) v = *(const float4*)(x + (size_t)row * CC + c4 * 4);
    else          v = *(const float4*)(m + (size_t)row * CC + (c4 - 128) * 4);
    *(float4*)(cat + (size_t)row * (2 * CC) + c4 * 4) = v;
}

// ---------------- launch ----------------
extern "C" void kernel_launch(void* const* d_in, const int* in_sizes, int n_in,
                              void* d_out, int out_size)
{
    const float* x  = (const float*)d_in[0];
    const float* y  = (const float*)d_in[1];
    const float* Wq = (const float*)d_in[2];
    const float* Wk = (const float*)d_in[3];
    const float* Wv = (const float*)d_in[4];
    const float* Wm = (const float*)d_in[5];
    const float* W1 = (const float*)d_in[6];
    const float* W2 = (const float*)d_in[7];
    const float* g1 = (const float*)d_in[8];
    const float* b1 = (const float*)d_in[9];
    const float* g2 = (const float*)d_in[10];
    const float* b2 = (const float*)d_in[11];
    float* out = (float*)d_out;

    float *Qb, *Kb, *Vb, *msgb, *m2b, *catb, *h1b, *h2b, *pKV, *pKs, *KVf, *Ksf;
    cudaGetSymbolAddress((void**)&Qb,   g_Q);
    cudaGetSymbolAddress((void**)&Kb,   g_K);
    cudaGetSymbolAddress((void**)&Vb,   g_V);
    cudaGetSymbolAddress((void**)&msgb, g_msg);
    cudaGetSymbolAddress((void**)&m2b,  g_m2);
    cudaGetSymbolAddress((void**)&catb, g_cat);
    cudaGetSymbolAddress((void**)&h1b,  g_h1);
    cudaGetSymbolAddress((void**)&h2b,  g_h2);
    cudaGetSymbolAddress((void**)&pKV,  g_pKV);
    cudaGetSymbolAddress((void**)&pKs,  g_pKs);
    cudaGetSymbolAddress((void**)&KVf,  g_KV);
    cudaGetSymbolAddress((void**)&Ksf,  g_Ks);

    const dim3 gP(CC / 128, ML / 128);        // 4 x 128 (N=512)
    const dim3 gW1(2 * CC / 128, ML / 128);   // 8 x 128 (N=1024)

    // projections
    sgemm_tn<1><<<gP, 256>>>(x, Wq, Qb, ML, CC, CC, 0.f);                 // Q = elu+1
    sgemm_tn<1><<<gP, 256>>>(y, Wk, Kb, ML, CC, CC, 0.f);                 // K = elu+1
    sgemm_tn<2><<<gP, 256>>>(y, Wv, Vb, ML, CC, CC, 1.f / (float)LL);     // V /= S

    // linear-attention aggregation
    kv_partial<<<dim3(NCH, HH, NB), 256>>>(Kb, Vb, pKV, pKs);
    kv_reduce<<<(NHT * HD * HD + NHT * HD + 255) / 256, 256>>>(pKV, pKs, KVf, Ksf);
    msg_kernel<<<dim3(LL / 64, HH, NB), 256>>>(Qb, KVf, Ksf, msgb);

    // message projection + LN1 (in-place; warp-local rows)
    sgemm_tn<0><<<gP, 256>>>(msgb, Wm, m2b, ML, CC, CC, 0.f);
    ln_kernel<<<ML * 32 / 256, 256>>>(m2b, m2b, g1, b1, nullptr);

    // MLP
    concat_kernel<<<ML * 256 / 256, 256>>>(x, m2b, catb);
    sgemm_tn<3><<<gW1, 256>>>(catb, W1, h1b, ML, 2 * CC, 2 * CC, 0.f);    // relu
    sgemm_tn<0><<<gP, 256>>>(h1b, W2, h2b, ML, CC, 2 * CC, 0.f);

    // LN2 + residual -> out
    ln_kernel<<<ML * 32 / 256, 256>>>(h2b, out, g2, b2, x);
}

// round 8
// speedup vs baseline: 4.4904x; 4.4904x over previous
#include <cuda_runtime.h>
#include <cuda_bf16.h>
#include <math.h>
#include <stdint.h>

typedef __nv_bfloat16  bf16;
typedef __nv_bfloat162 bf162;

#define NB 4
#define LL 4096
#define CC 512
#define HH 8
#define HD 64
#define ML (NB*LL)
#define NCH 32
#define NHT (NB*HH)

// ---------------- scratch ----------------
__device__ float g_Qf [ML*CC];
__device__ float g_Kf [ML*CC];
__device__ float g_Vf [ML*CC];
__device__ float g_m2 [ML*CC];
__device__ float g_h2 [ML*CC];
__device__ float g_pKV[NCH*NHT*HD*HD];
__device__ float g_pKs[NCH*NHT*HD];
__device__ float g_KVr[NHT*HD*HD];
__device__ float g_Ksr[NHT*HD];
__device__ bf16  g_cats[2ull*ML*2*CC];   // [hi|lo] planes of cat=[x|ln1(msg)]
__device__ bf16  g_ys  [2ull*ML*CC];
__device__ bf16  g_msgs[2ull*ML*CC];
__device__ bf16  g_h1s [2ull*ML*2*CC];
__device__ bf16  g_wqs [2*CC*CC];
__device__ bf16  g_wks [2*CC*CC];
__device__ bf16  g_wvs [2*CC*CC];
__device__ bf16  g_wms [2*CC*CC];
__device__ bf16  g_w1s [2*(2*CC)*(2*CC)];
__device__ bf16  g_w2s [2*CC*(2*CC)];

// ---------------- PTX helpers (baseline sm_103: cp.async/ldmatrix/mma only) ----------------
__device__ __forceinline__ uint32_t s2u(const void* p){ return (uint32_t)__cvta_generic_to_shared(p); }
__device__ __forceinline__ void cpa16(uint32_t d, const void* g){
    asm volatile("cp.async.cg.shared.global [%0], [%1], 16;" :: "r"(d), "l"(g));
}
__device__ __forceinline__ void cp_commit(){ asm volatile("cp.async.commit_group;" ::: "memory"); }
__device__ __forceinline__ void cp_wait1(){ asm volatile("cp.async.wait_group 1;" ::: "memory"); }
__device__ __forceinline__ void cp_wait0(){ asm volatile("cp.async.wait_group 0;" ::: "memory"); }
__device__ __forceinline__ uint32_t sw128(uint32_t o){ return o ^ ((o >> 3) & 0x70); }
__device__ __forceinline__ void ldm4(uint32_t& r0, uint32_t& r1, uint32_t& r2, uint32_t& r3, uint32_t a){
    asm volatile("ldmatrix.sync.aligned.m8n8.x4.shared.b16 {%0,%1,%2,%3}, [%4];"
                 : "=r"(r0), "=r"(r1), "=r"(r2), "=r"(r3) : "r"(a));
}
__device__ __forceinline__ void mma16816(float* c, const uint32_t* a, const uint32_t* b){
    asm volatile(
        "mma.sync.aligned.m16n8k16.row.col.f32.bf16.bf16.f32 "
        "{%0,%1,%2,%3}, {%4,%5,%6,%7}, {%8,%9}, {%0,%1,%2,%3};"
        : "+f"(c[0]), "+f"(c[1]), "+f"(c[2]), "+f"(c[3])
        : "r"(a[0]), "r"(a[1]), "r"(a[2]), "r"(a[3]), "r"(b[0]), "r"(b[1]));
}
__device__ __forceinline__ void split1(float v, bf16& h, bf16& l){
    h = __float2bfloat16(v);
    l = __float2bfloat16(v - __bfloat162float(h));
}

// ---------------- fp32 -> (hi,lo) bf16 split ----------------
__global__ void __launch_bounds__(256) split_kernel(
    const float* __restrict__ src, bf16* __restrict__ dh, bf16* __restrict__ dl,
    int srcCols, int dstCols, int colOff, int total4)
{
    int idx = blockIdx.x * 256 + threadIdx.x;
    if (idx >= total4) return;
    int c4pr = srcCols >> 2;
    int row = idx / c4pr;
    int c = (idx - row * c4pr) << 2;
    float4 v = *(const float4*)(src + (size_t)row * srcCols + c);
    size_t o = (size_t)row * dstCols + colOff + c;
    bf16 h0,h1,h2,h3,l0,l1,l2,l3;
    split1(v.x,h0,l0); split1(v.y,h1,l1); split1(v.z,h2,l2); split1(v.w,h3,l3);
    *(bf162*)(dh+o)   = __halves2bfloat162(h0,h1);
    *(bf162*)(dh+o+2) = __halves2bfloat162(h2,h3);
    *(bf162*)(dl+o)   = __halves2bfloat162(l0,l1);
    *(bf162*)(dl+o+2) = __halves2bfloat162(l2,l3);
}

// ---------------- HMMA split-bf16 GEMM: C[M,N] = A @ B^T ----------------
// Block 128x128, BK=64, 8 warps (2x4), warp tile 64x32, 3-term split accumulation.
#define STG_BYTES 65536
#define OFF_AH 0
#define OFF_AL 16384
#define OFF_BH 32768
#define OFF_BL 49152
#define TG_SMEM (2*STG_BYTES)

__device__ __forceinline__ void ld_tile(uint32_t dst, const bf16* src, int ld, int tid){
#pragma unroll
    for (int i = 0; i < 4; i++){                 // 1024 x 16B chunks, 256 threads
        int idx = i * 256 + tid;
        int r = idx >> 3, c = idx & 7;
        cpa16(dst + sw128((uint32_t)(r * 128 + c * 16)), src + (size_t)r * ld + c * 8);
    }
}
__device__ __forceinline__ void load_stage(
    uint32_t base, const bf16* Ah, const bf16* Al, const bf16* Bh, const bf16* Bl,
    int lda, int ldb, int m0, int n0, int k0, int tid)
{
    size_t ao = (size_t)m0 * lda + k0, bo = (size_t)n0 * ldb + k0;
    ld_tile(base + OFF_AH, Ah + ao, lda, tid);
    ld_tile(base + OFF_AL, Al + ao, lda, tid);
    ld_tile(base + OFF_BH, Bh + bo, ldb, tid);
    ld_tile(base + OFF_BL, Bl + bo, ldb, tid);
}

// EPI: 0 none, 1 elu+1, 2 *param, 3 relu.  SPLITOUT: write (hi,lo) bf16 planes.
template<int EPI, int SPLITOUT>
__global__ void __launch_bounds__(256) tc_gemm(
    const bf16* __restrict__ Ah, const bf16* __restrict__ Al,
    const bf16* __restrict__ Bh, const bf16* __restrict__ Bl,
    float* __restrict__ C, bf16* __restrict__ Ch, bf16* __restrict__ Cl,
    int N, int Klen, int lda, float param)
{
    extern __shared__ char smem[];
    const uint32_t sb = s2u(smem);
    const int tid = threadIdx.x;
    const int m0 = blockIdx.y * 128, n0 = blockIdx.x * 128;
    const int KT = Klen >> 6;
    const int w = tid >> 5, l = tid & 31;
    const int wm = (w >> 2) * 64;          // warp row offset in tile
    const int wn = (w & 3) * 32;           // warp col offset in tile

    // ldmatrix per-lane relative coords (non-trans; both operands K-contiguous)
    const int mat = l >> 3, lr = l & 7;
    const int a_r = ((mat & 1) << 3) + lr;     // A x4: (m0,k0),(m8,k0),(m0,k8),(m8,k8)
    const int a_c = (mat >> 1) << 3;
    const int b_r = ((mat >> 1) << 3) + lr;    // B x4: (n0,k0),(n0,k8),(n8,k0),(n8,k8)
    const int b_c = (mat & 1) << 3;

    float acc[4][4][4];
#pragma unroll
    for (int i = 0; i < 4; i++)
#pragma unroll
        for (int j = 0; j < 4; j++)
#pragma unroll
            for (int q = 0; q < 4; q++) acc[i][j][q] = 0.f;

    load_stage(sb,             Ah, Al, Bh, Bl, lda, Klen, m0, n0, 0, tid);
    cp_commit();
    if (KT > 1){
        load_stage(sb + STG_BYTES, Ah, Al, Bh, Bl, lda, Klen, m0, n0, 64, tid);
        cp_commit();
    }

    for (int kt = 0; kt < KT; kt++){
        if (kt + 1 < KT) cp_wait1(); else cp_wait0();
        __syncthreads();
        const uint32_t base = sb + (kt & 1) * STG_BYTES;
        const uint32_t sAH = base + OFF_AH, sAL = base + OFF_AL;
        const uint32_t sBH = base + OFF_BH, sBL = base + OFF_BL;
#pragma unroll
        for (int ks = 0; ks < 4; ks++){
            const int kb = ks * 16;
            uint32_t ah[4][4], al[4][4], bh[4][2], bl[4][2];
#pragma unroll
            for (int i = 0; i < 4; i++){
                uint32_t off = sw128((uint32_t)((wm + i*16 + a_r) * 128 + (kb + a_c) * 2));
                ldm4(ah[i][0], ah[i][1], ah[i][2], ah[i][3], sAH + off);
                ldm4(al[i][0], al[i][1], al[i][2], al[i][3], sAL + off);
            }
#pragma unroll
            for (int jj = 0; jj < 2; jj++){
                uint32_t off = sw128((uint32_t)((wn + jj*16 + b_r) * 128 + (kb + b_c) * 2));
                ldm4(bh[2*jj][0], bh[2*jj][1], bh[2*jj+1][0], bh[2*jj+1][1], sBH + off);
                ldm4(bl[2*jj][0], bl[2*jj][1], bl[2*jj+1][0], bl[2*jj+1][1], sBL + off);
            }
#pragma unroll
            for (int i = 0; i < 4; i++)
#pragma unroll
                for (int j = 0; j < 4; j++){
                    mma16816(acc[i][j], ah[i], bh[j]);
                    mma16816(acc[i][j], ah[i], bl[j]);
                    mma16816(acc[i][j], al[i], bh[j]);
                }
        }
        __syncthreads();
        if (kt + 2 < KT){
            load_stage(sb + (kt & 1) * STG_BYTES, Ah, Al, Bh, Bl,
                       lda, Klen, m0, n0, (kt + 2) * 64, tid);
            cp_commit();
        }
    }

    // epilogue: thread (g=l/4, t=l%4) holds C[g][2t,2t+1] and C[g+8][2t,2t+1] per tile
    const int g = l >> 2, t = l & 3;
#pragma unroll
    for (int i = 0; i < 4; i++){
#pragma unroll
        for (int j = 0; j < 4; j++){
#pragma unroll
            for (int half = 0; half < 2; half++){
                const int row = m0 + wm + i*16 + g + half*8;
                const int col = n0 + wn + j*8 + 2*t;
                float v0 = acc[i][j][half*2+0];
                float v1 = acc[i][j][half*2+1];
                if (EPI == 1){
                    v0 = (v0 > 0.f) ? (v0 + 1.f) : expf(v0);
                    v1 = (v1 > 0.f) ? (v1 + 1.f) : expf(v1);
                } else if (EPI == 2){ v0 *= param; v1 *= param; }
                else if (EPI == 3){ v0 = fmaxf(v0, 0.f); v1 = fmaxf(v1, 0.f); }
                if (!SPLITOUT){
                    *(float2*)(C + (size_t)row * N + col) = make_float2(v0, v1);
                } else {
                    size_t o = (size_t)row * N + col;
                    bf16 h0,h1,l0,l1;
                    split1(v0,h0,l0); split1(v1,h1,l1);
                    *(bf162*)(Ch + o) = __halves2bfloat162(h0,h1);
                    *(bf162*)(Cl + o) = __halves2bfloat162(l0,l1);
                }
            }
        }
    }
}

// -------- KV partial over 128-row chunks --------
__global__ void __launch_bounds__(256) kv_partial(
    const float* __restrict__ Kb, const float* __restrict__ Vb,
    float* __restrict__ pKV, float* __restrict__ pKs)
{
    __shared__ float Ks[32][64];
    __shared__ float Vs[32][64];
    const int tid = threadIdx.x;
    const int ch = blockIdx.x, h = blockIdx.y, n = blockIdx.z;
    const int nh = n * HH + h;
    const int CHR = LL / NCH;
    const float* Kp = Kb + ((size_t)n * LL + ch * CHR) * CC + h * HD;
    const float* Vp = Vb + ((size_t)n * LL + ch * CHR) * CC + h * HD;
    const int d0 = (tid >> 4) * 4, v0 = (tid & 15) * 4;
    float acc[4][4] = {};
    float ks[4] = {0.f,0.f,0.f,0.f};
    for (int s0 = 0; s0 < CHR; s0 += 32){
#pragma unroll
        for (int u = 0; u < 2; u++){
            int idx = tid * 2 + u;
            int r = idx >> 4, c4 = idx & 15;
            *(float4*)&Ks[r][c4*4] = *(const float4*)(Kp + (size_t)(s0+r)*CC + c4*4);
            *(float4*)&Vs[r][c4*4] = *(const float4*)(Vp + (size_t)(s0+r)*CC + c4*4);
        }
        __syncthreads();
#pragma unroll 8
        for (int s = 0; s < 32; s++){
            float4 kk = *(const float4*)&Ks[s][d0];
            float4 vv = *(const float4*)&Vs[s][v0];
            float ka[4] = {kk.x,kk.y,kk.z,kk.w};
            float va[4] = {vv.x,vv.y,vv.z,vv.w};
#pragma unroll
            for (int i = 0; i < 4; i++){
                ks[i] += ka[i];
#pragma unroll
                for (int j = 0; j < 4; j++) acc[i][j] += ka[i] * va[j];
            }
        }
        __syncthreads();
    }
    float* o = pKV + ((size_t)ch * NHT + nh) * HD * HD;
#pragma unroll
    for (int i = 0; i < 4; i++)
        *(float4*)(o + (d0+i)*HD + v0) = make_float4(acc[i][0],acc[i][1],acc[i][2],acc[i][3]);
    if ((tid & 15) == 0){
        float* ok = pKs + ((size_t)ch * NHT + nh) * HD + d0;
#pragma unroll
        for (int i = 0; i < 4; i++) ok[i] = ks[i];
    }
}

__global__ void kv_reduce(const float* __restrict__ pKV, const float* __restrict__ pKs,
                          float* __restrict__ KV, float* __restrict__ Ksum)
{
    const int idx = blockIdx.x * 256 + threadIdx.x;
    const int nKV = NHT * HD * HD;
    if (idx < nKV){
        float s = 0.f;
#pragma unroll
        for (int c = 0; c < NCH; c++) s += pKV[(size_t)c * nKV + idx];
        KV[idx] = s;
    } else if (idx < nKV + NHT * HD){
        int j = idx - nKV;
        float s = 0.f;
#pragma unroll
        for (int c = 0; c < NCH; c++) s += pKs[(size_t)c * NHT * HD + j];
        Ksum[j] = s;
    }
}

// -------- msg = (Q @ KV) * S/(Q.Ksum+eps), split-out --------
__global__ void __launch_bounds__(256) msg_kernel(
    const float* __restrict__ Q, const float* __restrict__ KV,
    const float* __restrict__ Ksum, bf16* __restrict__ mh, bf16* __restrict__ mlo)
{
    __shared__ float Qs[64][64];
    __shared__ float KVs[64][64];
    __shared__ float Kss[64];
    const int tid = threadIdx.x;
    const int lt = blockIdx.x, h = blockIdx.y, n = blockIdx.z;
    const int nh = n * HH + h;
    const float* Qp  = Q  + ((size_t)n * LL + lt * 64) * CC + h * HD;
    const float* KVp = KV + (size_t)nh * HD * HD;
#pragma unroll
    for (int u = 0; u < 4; u++){
        int idx = u * 256 + tid;
        int r = idx >> 4, c4 = idx & 15;
        *(float4*)&Qs[r][c4*4]  = *(const float4*)(Qp  + (size_t)r * CC + c4*4);
        *(float4*)&KVs[r][c4*4] = *(const float4*)(KVp + r * HD + c4*4);
    }
    if (tid < 64) Kss[tid] = Ksum[(size_t)nh * HD + tid];
    __syncthreads();
    const int r0 = (tid >> 4) * 4, c0 = (tid & 15) * 4;
    float acc[4][4] = {};
    float z[4] = {0.f,0.f,0.f,0.f};
#pragma unroll 16
    for (int k = 0; k < 64; k++){
        float4 bb = *(const float4*)&KVs[k][c0];
        float b[4] = {bb.x,bb.y,bb.z,bb.w};
        float ksk = Kss[k];
#pragma unroll
        for (int i = 0; i < 4; i++){
            float a = Qs[r0+i][k];
            z[i] += a * ksk;
#pragma unroll
            for (int j = 0; j < 4; j++) acc[i][j] += a * b[j];
        }
    }
#pragma unroll
    for (int i = 0; i < 4; i++){
        float sc = (float)LL / (z[i] + 1e-6f);
        size_t o = ((size_t)(n*LL + lt*64 + r0 + i)) * CC + h * HD + c0;
        bf16 h0,h1,h2,h3,l0,l1,l2,l3;
        split1(acc[i][0]*sc,h0,l0); split1(acc[i][1]*sc,h1,l1);
        split1(acc[i][2]*sc,h2,l2); split1(acc[i][3]*sc,h3,l3);
        *(bf162*)(mh +o)   = __halves2bfloat162(h0,h1);
        *(bf162*)(mh +o+2) = __halves2bfloat162(h2,h3);
        *(bf162*)(mlo+o)   = __halves2bfloat162(l0,l1);
        *(bf162*)(mlo+o+2) = __halves2bfloat162(l2,l3);
    }
}

// -------- LN1: fp32 in -> split bf16 into cat cols [512,1024) --------
__global__ void __launch_bounds__(256) ln_split(
    const float* __restrict__ in, bf16* __restrict__ oh, bf16* __restrict__ ol,
    const float* __restrict__ g, const float* __restrict__ b)
{
    const int row  = (blockIdx.x * 256 + threadIdx.x) >> 5;
    const int lane = threadIdx.x & 31;
    if (row >= ML) return;
    const float* p = in + (size_t)row * CC;
    float v[16];
#pragma unroll
    for (int u = 0; u < 4; u++){
        float4 t = *(const float4*)(p + u*128 + lane*4);
        v[u*4]=t.x; v[u*4+1]=t.y; v[u*4+2]=t.z; v[u*4+3]=t.w;
    }
    float s = 0.f, sq = 0.f;
#pragma unroll
    for (int i = 0; i < 16; i++){ s += v[i]; sq += v[i]*v[i]; }
#pragma unroll
    for (int off = 16; off >= 1; off >>= 1){
        s  += __shfl_xor_sync(0xFFFFFFFFu, s,  off);
        sq += __shfl_xor_sync(0xFFFFFFFFu, sq, off);
    }
    const float mu = s * (1.f/CC);
    const float rs = rsqrtf(sq*(1.f/CC) - mu*mu + 1e-5f);
#pragma unroll
    for (int u = 0; u < 4; u++){
        int c = u*128 + lane*4;
        float4 go = *(const float4*)(g + c);
        float4 bo = *(const float4*)(b + c);
        float r0 = (v[u*4]  -mu)*rs*go.x + bo.x;
        float r1 = (v[u*4+1]-mu)*rs*go.y + bo.y;
        float r2 = (v[u*4+2]-mu)*rs*go.z + bo.z;
        float r3 = (v[u*4+3]-mu)*rs*go.w + bo.w;
        size_t o = (size_t)row * 1024 + 512 + c;
        bf16 h0,h1,h2,h3,l0,l1,l2,l3;
        split1(r0,h0,l0); split1(r1,h1,l1); split1(r2,h2,l2); split1(r3,h3,l3);
        *(bf162*)(oh+o)   = __halves2bfloat162(h0,h1);
        *(bf162*)(oh+o+2) = __halves2bfloat162(h2,h3);
        *(bf162*)(ol+o)   = __halves2bfloat162(l0,l1);
        *(bf162*)(ol+o+2) = __halves2bfloat162(l2,l3);
    }
}

// -------- LN2 + residual -> fp32 out --------
__global__ void __launch_bounds__(256) ln_resid(
    const float* __restrict__ in, float* __restrict__ out,
    const float* __restrict__ g, const float* __restrict__ b,
    const float* __restrict__ resid)
{
    const int row  = (blockIdx.x * 256 + threadIdx.x) >> 5;
    const int lane = threadIdx.x & 31;
    if (row >= ML) return;
    const float* p = in + (size_t)row * CC;
    float v[16];
#pragma unroll
    for (int u = 0; u < 4; u++){
        float4 t = *(const float4*)(p + u*128 + lane*4);
        v[u*4]=t.x; v[u*4+1]=t.y; v[u*4+2]=t.z; v[u*4+3]=t.w;
    }
    float s = 0.f, sq = 0.f;
#pragma unroll
    for (int i = 0; i < 16; i++){ s += v[i]; sq += v[i]*v[i]; }
#pragma unroll
    for (int off = 16; off >= 1; off >>= 1){
        s  += __shfl_xor_sync(0xFFFFFFFFu, s,  off);
        sq += __shfl_xor_sync(0xFFFFFFFFu, sq, off);
    }
    const float mu = s * (1.f/CC);
    const float rs = rsqrtf(sq*(1.f/CC) - mu*mu + 1e-5f);
    float* o = out + (size_t)row * CC;
#pragma unroll
    for (int u = 0; u < 4; u++){
        int c = u*128 + lane*4;
        float4 go = *(const float4*)(g + c);
        float4 bo = *(const float4*)(b + c);
        float4 rx = *(const float4*)(resid + (size_t)row * CC + c);
        float4 r;
        r.x = (v[u*4]  -mu)*rs*go.x + bo.x + rx.x;
        r.y = (v[u*4+1]-mu)*rs*go.y + bo.y + rx.y;
        r.z = (v[u*4+2]-mu)*rs*go.z + bo.z + rx.z;
        r.w = (v[u*4+3]-mu)*rs*go.w + bo.w + rx.w;
        *(float4*)(o + c) = r;
    }
}

// ---------------- launch ----------------
extern "C" void kernel_launch(void* const* d_in, const int* in_sizes, int n_in,
                              void* d_out, int out_size)
{
    const float* x  = (const float*)d_in[0];
    const float* y  = (const float*)d_in[1];
    const float* Wq = (const float*)d_in[2];
    const float* Wk = (const float*)d_in[3];
    const float* Wv = (const float*)d_in[4];
    const float* Wm = (const float*)d_in[5];
    const float* W1 = (const float*)d_in[6];
    const float* W2 = (const float*)d_in[7];
    const float* g1 = (const float*)d_in[8];
    const float* b1 = (const float*)d_in[9];
    const float* g2 = (const float*)d_in[10];
    const float* b2 = (const float*)d_in[11];
    float* out = (float*)d_out;

    float *Qf,*Kf,*Vf,*m2,*h2,*pKV,*pKs,*KVr,*Ksr;
    bf16 *cats,*ys,*msgs,*h1s,*wqs,*wks,*wvs,*wms,*w1s,*w2s;
    cudaGetSymbolAddress((void**)&Qf, g_Qf);  cudaGetSymbolAddress((void**)&Kf, g_Kf);
    cudaGetSymbolAddress((void**)&Vf, g_Vf);  cudaGetSymbolAddress((void**)&m2, g_m2);
    cudaGetSymbolAddress((void**)&h2, g_h2);  cudaGetSymbolAddress((void**)&pKV, g_pKV);
    cudaGetSymbolAddress((void**)&pKs, g_pKs); cudaGetSymbolAddress((void**)&KVr, g_KVr);
    cudaGetSymbolAddress((void**)&Ksr, g_Ksr); cudaGetSymbolAddress((void**)&cats, g_cats);
    cudaGetSymbolAddress((void**)&ys, g_ys);  cudaGetSymbolAddress((void**)&msgs, g_msgs);
    cudaGetSymbolAddress((void**)&h1s, g_h1s); cudaGetSymbolAddress((void**)&wqs, g_wqs);
    cudaGetSymbolAddress((void**)&wks, g_wks); cudaGetSymbolAddress((void**)&wvs, g_wvs);
    cudaGetSymbolAddress((void**)&wms, g_wms); cudaGetSymbolAddress((void**)&w1s, g_w1s);
    cudaGetSymbolAddress((void**)&w2s, g_w2s);

    bf16 *catH = cats, *catL = cats + (size_t)ML*1024;
    bf16 *ysH = ys,   *ysL = ys  + (size_t)ML*CC;
    bf16 *msH = msgs, *msL = msgs + (size_t)ML*CC;
    bf16 *h1H = h1s,  *h1L = h1s + (size_t)ML*1024;
    bf16 *wqH=wqs,*wqL=wqs+CC*CC, *wkH=wks,*wkL=wks+CC*CC;
    bf16 *wvH=wvs,*wvL=wvs+CC*CC, *wmH=wms,*wmL=wms+CC*CC;
    bf16 *w1H=w1s,*w1L=w1s+(2*CC)*(2*CC), *w2H=w2s,*w2L=w2s+CC*(2*CC);

    cudaFuncSetAttribute(tc_gemm<0,0>, cudaFuncAttributeMaxDynamicSharedMemorySize, TG_SMEM);
    cudaFuncSetAttribute(tc_gemm<1,0>, cudaFuncAttributeMaxDynamicSharedMemorySize, TG_SMEM);
    cudaFuncSetAttribute(tc_gemm<2,0>, cudaFuncAttributeMaxDynamicSharedMemorySize, TG_SMEM);
    cudaFuncSetAttribute(tc_gemm<3,1>, cudaFuncAttributeMaxDynamicSharedMemorySize, TG_SMEM);

    // splits
    int t;
    t = ML*CC/4;      split_kernel<<<(t+255)/256,256>>>(x, catH, catL, 512, 1024, 0, t);
                      split_kernel<<<(t+255)/256,256>>>(y, ysH, ysL, 512, 512, 0, t);
    t = CC*CC/4;      split_kernel<<<(t+255)/256,256>>>(Wq, wqH, wqL, 512, 512, 0, t);
                      split_kernel<<<(t+255)/256,256>>>(Wk, wkH, wkL, 512, 512, 0, t);
                      split_kernel<<<(t+255)/256,256>>>(Wv, wvH, wvL, 512, 512, 0, t);
                      split_kernel<<<(t+255)/256,256>>>(Wm, wmH, wmL, 512, 512, 0, t);
    t = 4*CC*CC/4;    split_kernel<<<(t+255)/256,256>>>(W1, w1H, w1L, 1024, 1024, 0, t);
    t = 2*CC*CC/4;    split_kernel<<<(t+255)/256,256>>>(W2, w2H, w2L, 1024, 1024, 0, t);

    const dim3 gP(4, ML/128), gW1(8, ML/128);

    // projections (x split lives in cat cols 0..511, lda=1024)
    tc_gemm<1,0><<<gP, 256, TG_SMEM>>>(catH, catL, wqH, wqL, Qf, 0, 0, 512, 512, 1024, 0.f);
    tc_gemm<1,0><<<gP, 256, TG_SMEM>>>(ysH, ysL, wkH, wkL, Kf, 0, 0, 512, 512, 512, 0.f);
    tc_gemm<2,0><<<gP, 256, TG_SMEM>>>(ysH, ysL, wvH, wvL, Vf, 0, 0, 512, 512, 512, 1.f/(float)LL);

    // linear attention
    kv_partial<<<dim3(NCH, HH, NB), 256>>>(Kf, Vf, pKV, pKs);
    kv_reduce<<<(NHT*HD*HD + NHT*HD + 255)/256, 256>>>(pKV, pKs, KVr, Ksr);
    msg_kernel<<<dim3(LL/64, HH, NB), 256>>>(Qf, KVr, Ksr, msH, msL);

    // message proj + LN1 into cat cols 512..1023
    tc_gemm<0,0><<<gP, 256, TG_SMEM>>>(msH, msL, wmH, wmL, m2, 0, 0, 512, 512, 512, 0.f);
    ln_split<<<ML*32/256, 256>>>(m2, catH, catL, g1, b1);

    // MLP
    tc_gemm<3,1><<<gW1, 256, TG_SMEM>>>(catH, catL, w1H, w1L, 0, h1H, h1L, 1024, 1024, 1024, 0.f);
    tc_gemm<0,0><<<gP, 256, TG_SMEM>>>(h1H, h1L, w2H, w2L, h2, 0, 0, 512, 1024, 1024, 0.f);

    // LN2 + residual
    ln_resid<<<ML*32/256, 256>>>(h2, out, g2, b2, x);
}